// round 14
// baseline (speedup 1.0000x reference)
#include <cuda_runtime.h>
#include <math.h>
#include <stdint.h>

#define BB 4
#define SS 4096
#define EE 512
#define HH 8
#define DD 64
#define WW 256
#define BHN (BB*HH)
#define NEG (-1e30f)

// Scratch q/k/v in [b*H+h][s][d] layout (q pre-scaled by 1/sqrt(D))
__device__ float g_q[(size_t)BHN * SS * DD];
__device__ float g_k[(size_t)BHN * SS * DD];
__device__ float g_v[(size_t)BHN * SS * DD];

__device__ __forceinline__ uint32_t f2tf(float f) {
    uint32_t u;
    asm("cvt.rna.tf32.f32 %0, %1;" : "=r"(u) : "f"(f));
    return u;
}

// m16n8k8 tf32 mma, fp32 accumulate. A row-major, B col-major.
__device__ __forceinline__ void mma8(float* c,
                                     uint32_t a0, uint32_t a1, uint32_t a2, uint32_t a3,
                                     uint32_t b0, uint32_t b1) {
    asm volatile(
        "mma.sync.aligned.m16n8k8.row.col.f32.tf32.tf32.f32 "
        "{%0,%1,%2,%3},{%4,%5,%6,%7},{%8,%9},{%0,%1,%2,%3};"
        : "+f"(c[0]), "+f"(c[1]), "+f"(c[2]), "+f"(c[3])
        : "r"(a0), "r"(a1), "r"(a2), "r"(a3), "r"(b0), "r"(b1));
}

// ---------------------------------------------------------------------------
// Fused projection GEMMs (tf32): blockIdx.z in {0,1,2} = Q,K,V.
// C = (X @ W^T + bias) * scale -> Out[b*H+h][s][d].
// R9 fragment-slot layout + NEW double buffering with COMPILE-TIME buffer
// selection (k-loop unrolled by 2): one sync per k-chunk, STS of chunk k+1
// overlaps other warps' mma tail of chunk k.  All smem addresses are
// base + literal offset (no runtime pointer selection — the R11 mistake).
// ---------------------------------------------------------------------------
#define PIDX(f, s, ln) ((((f) * 4 + (s)) * 32 + (ln)) * 4)
#define SMEM_PROJ (64 * 1024)

__global__ __launch_bounds__(256, 2)
void proj_mma(const float* __restrict__ Xq, const float* __restrict__ Xk,
              const float* __restrict__ Xv,
              const float* __restrict__ Wq, const float* __restrict__ Wk,
              const float* __restrict__ Wv,
              const float* __restrict__ bq, const float* __restrict__ bk,
              const float* __restrict__ bv,
              float* __restrict__ Oq, float* __restrict__ Ok,
              float* __restrict__ Ov)
{
    extern __shared__ uint32_t psm[];
    // Compile-time constant offsets: A0 | A1 | B0 | B1, 16KB each.
    uint32_t* const A0 = psm;
    uint32_t* const A1 = psm + 4096;
    uint32_t* const B0 = psm + 8192;
    uint32_t* const B1 = psm + 12288;

    const int z = blockIdx.z;
    const float* X    = (z == 0) ? Xq : (z == 1) ? Xk : Xv;
    const float* Wm   = (z == 0) ? Wq : (z == 1) ? Wk : Wv;
    const float* bias = (z == 0) ? bq : (z == 1) ? bk : bv;
    float*       Out  = (z == 0) ? Oq : (z == 1) ? Ok : Ov;
    const float scale = (z == 0) ? 0.125f : 1.0f;

    const int tid = threadIdx.x;
    const int lane = tid & 31;
    const int w = tid >> 5;
    const int wm = w >> 2;
    const int wn = w & 3;
    const int m0 = blockIdx.y * 128;
    const int n0 = blockIdx.x * 128;
    const int g = lane >> 2;
    const int t = lane & 3;

    float acc[4][4][4];
#pragma unroll
    for (int mt = 0; mt < 4; mt++)
#pragma unroll
        for (int nt = 0; nt < 4; nt++)
#pragma unroll
            for (int i = 0; i < 4; i++) acc[mt][nt][i] = 0.f;

    // Per-thread fragment-slot base pointers.
    const float* aBase[4];
    const float* bBase[4];
#pragma unroll
    for (int p = 0; p < 4; p++) {
        int pair = w * 4 + p;
        int mt = pair >> 2, s = pair & 3;
        aBase[p] = X + (size_t)(m0 + mt * 16 + g) * EE + 8 * s + 2 * t;
    }
#pragma unroll
    for (int p = 0; p < 4; p++) {
        int slot = w * 4 + p;
        int np = slot >> 2, s = slot & 3;
        bBase[p] = Wm + (size_t)(n0 + np * 16 + g) * EE + 8 * s + 2 * t;
    }

    float2 pa0[4], pa1[4], pb0[4], pb1[4];
    // Prefetch chunk 0, store into buffer 0, one sync.
#pragma unroll
    for (int p = 0; p < 4; p++) {
        pa0[p] = *(const float2*)(aBase[p]);
        pa1[p] = *(const float2*)(aBase[p] + 8 * EE);
        pb0[p] = *(const float2*)(bBase[p]);
        pb1[p] = *(const float2*)(bBase[p] + 8 * EE);
    }
#pragma unroll
    for (int p = 0; p < 4; p++) {
        int pair = w * 4 + p;
        int f = pair >> 2, s = pair & 3;
        uint4 u;
        u.x = f2tf(pa0[p].x); u.y = f2tf(pa1[p].x);
        u.z = f2tf(pa0[p].y); u.w = f2tf(pa1[p].y);
        *(uint4*)&A0[PIDX(f, s, lane)] = u;
        uint4 v;
        v.x = f2tf(pb0[p].x); v.y = f2tf(pb0[p].y);
        v.z = f2tf(pb1[p].x); v.w = f2tf(pb1[p].y);
        *(uint4*)&B0[PIDX(f, s, lane)] = v;
    }
    __syncthreads();

    for (int kc2 = 0; kc2 < 8; kc2++) {
#pragma unroll
        for (int half = 0; half < 2; half++) {
            const int kc = kc2 * 2 + half;
            uint32_t* const cA = half ? A1 : A0;   // compile-time constant
            uint32_t* const cB = half ? B1 : B0;
            uint32_t* const nA = half ? A0 : A1;
            uint32_t* const nB = half ? B0 : B1;
            const bool more = (kc + 1 < 16);

            // Prefetch chunk kc+1 into registers (overlaps mma below).
            if (more) {
                const int koff = (kc + 1) * 32;
#pragma unroll
                for (int p = 0; p < 4; p++) {
                    pa0[p] = *(const float2*)(aBase[p] + koff);
                    pa1[p] = *(const float2*)(aBase[p] + koff + 8 * EE);
                    pb0[p] = *(const float2*)(bBase[p] + koff);
                    pb1[p] = *(const float2*)(bBase[p] + koff + 8 * EE);
                }
            }

            // Compute chunk kc from current buffers.
#pragma unroll
            for (int s = 0; s < 4; s++) {
                uint4 bf0 = *(const uint4*)&cB[PIDX(wn * 2 + 0, s, lane)];
                uint4 bf1 = *(const uint4*)&cB[PIDX(wn * 2 + 1, s, lane)];
#pragma unroll
                for (int mt = 0; mt < 4; mt++) {
                    uint4 af = *(const uint4*)&cA[PIDX(wm * 4 + mt, s, lane)];
                    mma8(acc[mt][0], af.x, af.y, af.z, af.w, bf0.x, bf0.y);
                    mma8(acc[mt][1], af.x, af.y, af.z, af.w, bf0.z, bf0.w);
                    mma8(acc[mt][2], af.x, af.y, af.z, af.w, bf1.x, bf1.y);
                    mma8(acc[mt][3], af.x, af.y, af.z, af.w, bf1.z, bf1.w);
                }
            }

            // Store chunk kc+1 into the other buffers, then ONE sync.
            if (more) {
#pragma unroll
                for (int p = 0; p < 4; p++) {
                    int pair = w * 4 + p;
                    int f = pair >> 2, s = pair & 3;
                    uint4 u;
                    u.x = f2tf(pa0[p].x); u.y = f2tf(pa1[p].x);
                    u.z = f2tf(pa0[p].y); u.w = f2tf(pa1[p].y);
                    *(uint4*)&nA[PIDX(f, s, lane)] = u;
                    uint4 v;
                    v.x = f2tf(pb0[p].x); v.y = f2tf(pb0[p].y);
                    v.z = f2tf(pb1[p].x); v.w = f2tf(pb1[p].y);
                    *(uint4*)&nB[PIDX(f, s, lane)] = v;
                }
                __syncthreads();
            }
        }
    }

    // Epilogue: bias + scale, permuted store.
#pragma unroll
    for (int mt = 0; mt < 4; mt++) {
        int r0 = m0 + wm * 64 + mt * 16 + g;
        int r1 = r0 + 8;
        int b0i = r0 >> 12, s0i = r0 & (SS - 1);
        int b1i = r1 >> 12, s1i = r1 & (SS - 1);
#pragma unroll
        for (int nt = 0; nt < 4; nt++) {
            int n = n0 + wn * 32 + nt * 8 + 2 * t;
            int h = n >> 6, d = n & 63;
            float2 bi = *(const float2*)(bias + n);
            float2 o;
            o.x = (acc[mt][nt][0] + bi.x) * scale;
            o.y = (acc[mt][nt][1] + bi.y) * scale;
            *(float2*)(&Out[((size_t)(b0i * HH + h) * SS + s0i) * DD + d]) = o;
            o.x = (acc[mt][nt][2] + bi.x) * scale;
            o.y = (acc[mt][nt][3] + bi.y) * scale;
            *(float2*)(&Out[((size_t)(b1i * HH + h) * SS + s1i) * DD + d]) = o;
        }
    }
}

// ---------------------------------------------------------------------------
// Band attention (tf32 mma.sync) — R13 verbatim (160.4us, known good):
// 128-query-row blocks, Q rna-staged once, K/V raw-f32-bit staging,
// direct exp, P in registers, single epilogue row-sum reduction.
// ---------------------------------------------------------------------------
#define QIDX(s, mq, ln) ((((s) * 8 + (mq)) * 32 + (ln)) * 4)
#define KIDX(s, np, ln) ((((s) * 4 + (np)) * 32 + (ln)) * 4)
#define SMEM_ATTN (64 * 1024)

__global__ __launch_bounds__(128)
void attn_mma(float* __restrict__ out)
{
    extern __shared__ uint32_t dsm[];
    uint32_t* Qf = dsm;                 // [s][mq][lane][4]
    uint32_t* Kf = dsm + 8192;          // [s][np][lane][4]
    uint32_t* Vf = dsm + 12288;         // [s][np][lane][4]

    const int bh = blockIdx.y;
    const int bb = bh >> 3;
    const int hh = bh & 7;
    const int i0 = blockIdx.x * 128;
    const int tid = threadIdx.x;
    const int w = tid >> 5;
    const int lane = tid & 31;
    const int g = lane >> 2;
    const int t = lane & 3;

    const float* qg = g_q + (size_t)bh * SS * DD;
    const float* kg = g_k + (size_t)bh * SS * DD;
    const float* vg = g_v + (size_t)bh * SS * DD;

    // Stage Q once (round-to-nearest tf32).
#pragma unroll
    for (int p = 0; p < 16; p++) {
        int slot = w * 16 + p;
        int mq = slot >> 3, s = slot & 7;
        const float* r0 = qg + (size_t)(i0 + 16 * mq + g) * DD + 8 * s + 2 * t;
        float2 x0 = *(const float2*)r0;
        float2 x1 = *(const float2*)(r0 + 8 * DD);
        uint4 u;
        u.x = f2tf(x0.x); u.y = f2tf(x1.x);
        u.z = f2tf(x0.y); u.w = f2tf(x1.y);
        *(uint4*)&Qf[QIDX(s, mq, lane)] = u;
    }

    float oacc[2][8][4];
#pragma unroll
    for (int mt = 0; mt < 2; mt++)
#pragma unroll
        for (int nt = 0; nt < 8; nt++)
#pragma unroll
            for (int i = 0; i < 4; i++) oacc[mt][nt][i] = 0.f;
    float lpA[2] = {0.f, 0.f}, lpB[2] = {0.f, 0.f};   // per-lane partial sums

    for (int cg = 0; cg < 10; cg++) {
        int j0 = i0 - WW + cg * 64;
        if (j0 < 0 || j0 >= SS) continue;   // uniform per block

        __syncthreads();   // prior reads done before restage

        const float* kp = kg + (size_t)j0 * DD;
        const float* vp = vg + (size_t)j0 * DD;
        // K slots: raw f32 bits (LDG.64 -> STS.128, no cvt).
#pragma unroll
        for (int p = 0; p < 8; p++) {
            int slot = w * 8 + p;
            int np = slot >> 3, s = slot & 7;
            const float* r0 = kp + (size_t)(16 * np + g) * DD + 8 * s + 2 * t;
            float2 x0 = *(const float2*)r0;
            float2 x1 = *(const float2*)(r0 + 8 * DD);
            uint4 u;
            u.x = __float_as_uint(x0.x); u.y = __float_as_uint(x0.y);
            u.z = __float_as_uint(x1.x); u.w = __float_as_uint(x1.y);
            *(uint4*)&Kf[KIDX(s, np, lane)] = u;
        }
        // V slots: raw f32 bits.
#pragma unroll
        for (int p = 0; p < 8; p++) {
            int slot = w * 8 + p;
            int np = slot >> 3, s = slot & 7;
            const float* r0 = vp + (size_t)(8 * s + 2 * t) * DD;
            const float* r1 = r0 + DD;
            uint4 u;
            u.x = __float_as_uint(r0[16 * np + g]);
            u.y = __float_as_uint(r1[16 * np + g]);
            u.z = __float_as_uint(r0[16 * np + 8 + g]);
            u.w = __float_as_uint(r1[16 * np + 8 + g]);
            *(uint4*)&Vf[KIDX(s, np, lane)] = u;
        }
        __syncthreads();

        // QK: S = Q @ K^T  (32 rows x 64 cols per warp)
        float sc[2][8][4];
#pragma unroll
        for (int mt = 0; mt < 2; mt++)
#pragma unroll
            for (int nt = 0; nt < 8; nt++)
#pragma unroll
                for (int i = 0; i < 4; i++) sc[mt][nt][i] = 0.f;
#pragma unroll
        for (int s = 0; s < 8; s++) {
            uint4 q0 = *(const uint4*)&Qf[QIDX(s, 2 * w + 0, lane)];
            uint4 q1 = *(const uint4*)&Qf[QIDX(s, 2 * w + 1, lane)];
#pragma unroll
            for (int np = 0; np < 4; np++) {
                uint4 u = *(const uint4*)&Kf[KIDX(s, np, lane)];
                mma8(sc[0][2 * np],     q0.x, q0.y, q0.z, q0.w, u.x, u.y);
                mma8(sc[0][2 * np + 1], q0.x, q0.y, q0.z, q0.w, u.z, u.w);
                mma8(sc[1][2 * np],     q1.x, q1.y, q1.z, q1.w, u.x, u.y);
                mma8(sc[1][2 * np + 1], q1.x, q1.y, q1.z, q1.w, u.z, u.w);
            }
        }

        // Band mask: valid iff 0 <= 64*cg + col - row <= 512.
        if (cg <= 1) {
#pragma unroll
            for (int mt = 0; mt < 2; mt++) {
                int lo = 32 * w + 16 * mt + g - 64 * cg;
#pragma unroll
                for (int nt = 0; nt < 8; nt++) {
                    int c0 = 8 * nt + 2 * t;
                    if (c0     < lo)     sc[mt][nt][0] = NEG;
                    if (c0 + 1 < lo)     sc[mt][nt][1] = NEG;
                    if (c0     < lo + 8) sc[mt][nt][2] = NEG;
                    if (c0 + 1 < lo + 8) sc[mt][nt][3] = NEG;
                }
            }
        } else if (cg >= 8) {
#pragma unroll
            for (int mt = 0; mt < 2; mt++) {
                int hi = 32 * w + 16 * mt + g + 512 - 64 * cg;
#pragma unroll
                for (int nt = 0; nt < 8; nt++) {
                    int c0 = 8 * nt + 2 * t;
                    if (c0     > hi)     sc[mt][nt][0] = NEG;
                    if (c0 + 1 > hi)     sc[mt][nt][1] = NEG;
                    if (c0     > hi + 8) sc[mt][nt][2] = NEG;
                    if (c0 + 1 > hi + 8) sc[mt][nt][3] = NEG;
                }
            }
        }

        // Direct exp (scores bounded; masked -> exp(-1e30) == 0 exactly).
#pragma unroll
        for (int mt = 0; mt < 2; mt++) {
#pragma unroll
            for (int nt = 0; nt < 8; nt++) {
                sc[mt][nt][0] = __expf(sc[mt][nt][0]);
                sc[mt][nt][1] = __expf(sc[mt][nt][1]);
                sc[mt][nt][2] = __expf(sc[mt][nt][2]);
                sc[mt][nt][3] = __expf(sc[mt][nt][3]);
                lpA[mt] += sc[mt][nt][0] + sc[mt][nt][1];
                lpB[mt] += sc[mt][nt][2] + sc[mt][nt][3];
            }
        }

        // PV: O += P @ V.  P stays in registers (cvt.rna kept).
#pragma unroll
        for (int s = 0; s < 8; s++) {
            uint32_t a[2][4];
#pragma unroll
            for (int mt = 0; mt < 2; mt++) {
                a[mt][0] = f2tf(sc[mt][s][0]);
                a[mt][1] = f2tf(sc[mt][s][2]);
                a[mt][2] = f2tf(sc[mt][s][1]);
                a[mt][3] = f2tf(sc[mt][s][3]);
            }
#pragma unroll
            for (int np = 0; np < 4; np++) {
                uint4 u = *(const uint4*)&Vf[KIDX(s, np, lane)];
                mma8(oacc[0][2 * np],     a[0][0], a[0][1], a[0][2], a[0][3], u.x, u.y);
                mma8(oacc[0][2 * np + 1], a[0][0], a[0][1], a[0][2], a[0][3], u.z, u.w);
                mma8(oacc[1][2 * np],     a[1][0], a[1][1], a[1][2], a[1][3], u.x, u.y);
                mma8(oacc[1][2 * np + 1], a[1][0], a[1][1], a[1][2], a[1][3], u.z, u.w);
            }
        }
    }

    // Epilogue: quad-reduce row sums once, then scaled stores.
#pragma unroll
    for (int mt = 0; mt < 2; mt++) {
        float sA = lpA[mt], sB = lpB[mt];
        sA += __shfl_xor_sync(0xffffffffu, sA, 1);
        sA += __shfl_xor_sync(0xffffffffu, sA, 2);
        sB += __shfl_xor_sync(0xffffffffu, sB, 1);
        sB += __shfl_xor_sync(0xffffffffu, sB, 2);
        float iA = 1.f / sA, iB = 1.f / sB;
        size_t baseA = (size_t)(i0 + 32 * w + 16 * mt + g) * 2048
                     + (size_t)(bb * 512 + hh * 64);
        size_t baseB = baseA + (size_t)8 * 2048;
#pragma unroll
        for (int nt = 0; nt < 8; nt++) {
            int d = 8 * nt + 2 * t;
            float2 o;
            o.x = oacc[mt][nt][0] * iA; o.y = oacc[mt][nt][1] * iA;
            *(float2*)(out + baseA + d) = o;
            o.x = oacc[mt][nt][2] * iB; o.y = oacc[mt][nt][3] * iB;
            *(float2*)(out + baseB + d) = o;
        }
    }
}

// ---------------------------------------------------------------------------
extern "C" void kernel_launch(void* const* d_in, const int* in_sizes, int n_in,
                              void* d_out, int out_size)
{
    (void)in_sizes; (void)n_in; (void)out_size;
    const float* query = (const float*)d_in[0];
    const float* key   = (const float*)d_in[1];
    const float* value = (const float*)d_in[2];
    const float* Wq = (const float*)d_in[4];
    const float* bq = (const float*)d_in[5];
    const float* Wk = (const float*)d_in[6];
    const float* bk = (const float*)d_in[7];
    const float* Wv = (const float*)d_in[8];
    const float* bv = (const float*)d_in[9];
    float* out = (float*)d_out;

    float *qp, *kp, *vp;
    cudaGetSymbolAddress((void**)&qp, g_q);
    cudaGetSymbolAddress((void**)&kp, g_k);
    cudaGetSymbolAddress((void**)&vp, g_v);

    static int smem_set = 0;
    if (!smem_set) {
        cudaFuncSetAttribute(proj_mma,
                             cudaFuncAttributeMaxDynamicSharedMemorySize,
                             SMEM_PROJ);
        cudaFuncSetAttribute(attn_mma,
                             cudaFuncAttributeMaxDynamicSharedMemorySize,
                             SMEM_ATTN);
        smem_set = 1;
    }

    dim3 gp(EE / 128, (BB * SS) / 128, 3);   // fused Q/K/V projections
    proj_mma<<<gp, 256, SMEM_PROJ>>>(query, key, value, Wq, Wk, Wv,
                                     bq, bk, bv, qp, kp, vp);

    attn_mma<<<dim3(SS / 128, BHN), 128, SMEM_ATTN>>>(out);
}

// round 15
// speedup vs baseline: 1.0209x; 1.0209x over previous
#include <cuda_runtime.h>
#include <math.h>
#include <stdint.h>

#define BB 4
#define SS 4096
#define EE 512
#define HH 8
#define DD 64
#define WW 256
#define BHN (BB*HH)
#define NEG (-1e30f)

// Scratch q/k/v in [b*H+h][s][d] layout (q pre-scaled by 1/sqrt(D))
__device__ float g_q[(size_t)BHN * SS * DD];
__device__ float g_k[(size_t)BHN * SS * DD];
__device__ float g_v[(size_t)BHN * SS * DD];

__device__ __forceinline__ uint32_t f2tf(float f) {
    uint32_t u;
    asm("cvt.rna.tf32.f32 %0, %1;" : "=r"(u) : "f"(f));
    return u;
}

// m16n8k8 tf32 mma, fp32 accumulate. A row-major, B col-major.
__device__ __forceinline__ void mma8(float* c,
                                     uint32_t a0, uint32_t a1, uint32_t a2, uint32_t a3,
                                     uint32_t b0, uint32_t b1) {
    asm volatile(
        "mma.sync.aligned.m16n8k8.row.col.f32.tf32.tf32.f32 "
        "{%0,%1,%2,%3},{%4,%5,%6,%7},{%8,%9},{%0,%1,%2,%3};"
        : "+f"(c[0]), "+f"(c[1]), "+f"(c[2]), "+f"(c[3])
        : "r"(a0), "r"(a1), "r"(a2), "r"(a3), "r"(b0), "r"(b1));
}

// ---------------------------------------------------------------------------
// Fused projection GEMMs (tf32) — R9/R13 static version verbatim (~238us).
// ---------------------------------------------------------------------------
__global__ __launch_bounds__(256, 2)
void proj_mma(const float* __restrict__ Xq, const float* __restrict__ Xk,
              const float* __restrict__ Xv,
              const float* __restrict__ Wq, const float* __restrict__ Wk,
              const float* __restrict__ Wv,
              const float* __restrict__ bq, const float* __restrict__ bk,
              const float* __restrict__ bv,
              float* __restrict__ Oq, float* __restrict__ Ok,
              float* __restrict__ Ov)
{
    __shared__ uint32_t Ap[8][4][32][4];
    __shared__ uint32_t Bp[8][4][32][4];

    const int z = blockIdx.z;
    const float* X    = (z == 0) ? Xq : (z == 1) ? Xk : Xv;
    const float* Wm   = (z == 0) ? Wq : (z == 1) ? Wk : Wv;
    const float* bias = (z == 0) ? bq : (z == 1) ? bk : bv;
    float*       Out  = (z == 0) ? Oq : (z == 1) ? Ok : Ov;
    const float scale = (z == 0) ? 0.125f : 1.0f;

    const int tid = threadIdx.x;
    const int lane = tid & 31;
    const int w = tid >> 5;
    const int wm = w >> 2;
    const int wn = w & 3;
    const int m0 = blockIdx.y * 128;
    const int n0 = blockIdx.x * 128;
    const int g = lane >> 2;
    const int t = lane & 3;

    float acc[4][4][4];
#pragma unroll
    for (int mt = 0; mt < 4; mt++)
#pragma unroll
        for (int nt = 0; nt < 4; nt++)
#pragma unroll
            for (int i = 0; i < 4; i++) acc[mt][nt][i] = 0.f;

    const float* aBase[4];
    const float* bBase[4];
#pragma unroll
    for (int p = 0; p < 4; p++) {
        int pair = w * 4 + p;
        int mt = pair >> 2, s = pair & 3;
        aBase[p] = X + (size_t)(m0 + mt * 16 + g) * EE + 8 * s + 2 * t;
    }
#pragma unroll
    for (int p = 0; p < 4; p++) {
        int slot = w * 4 + p;
        int np = slot >> 2, s = slot & 3;
        bBase[p] = Wm + (size_t)(n0 + np * 16 + g) * EE + 8 * s + 2 * t;
    }

    float2 pa0[4], pa1[4], pb0[4], pb1[4];
#pragma unroll
    for (int p = 0; p < 4; p++) {
        pa0[p] = *(const float2*)(aBase[p]);
        pa1[p] = *(const float2*)(aBase[p] + 8 * EE);
        pb0[p] = *(const float2*)(bBase[p]);
        pb1[p] = *(const float2*)(bBase[p] + 8 * EE);
    }

    for (int kc = 0; kc < 16; kc++) {
#pragma unroll
        for (int p = 0; p < 4; p++) {
            int pair = w * 4 + p;
            int mt = pair >> 2, s = pair & 3;
            uint4 u;
            u.x = f2tf(pa0[p].x);
            u.y = f2tf(pa1[p].x);
            u.z = f2tf(pa0[p].y);
            u.w = f2tf(pa1[p].y);
            *(uint4*)&Ap[mt][s][lane][0] = u;
        }
#pragma unroll
        for (int p = 0; p < 4; p++) {
            int slot = w * 4 + p;
            int np = slot >> 2, s = slot & 3;
            uint4 u;
            u.x = f2tf(pb0[p].x);
            u.y = f2tf(pb0[p].y);
            u.z = f2tf(pb1[p].x);
            u.w = f2tf(pb1[p].y);
            *(uint4*)&Bp[np][s][lane][0] = u;
        }
        __syncthreads();

        if (kc + 1 < 16) {
            const int koff = (kc + 1) * 32;
#pragma unroll
            for (int p = 0; p < 4; p++) {
                pa0[p] = *(const float2*)(aBase[p] + koff);
                pa1[p] = *(const float2*)(aBase[p] + koff + 8 * EE);
                pb0[p] = *(const float2*)(bBase[p] + koff);
                pb1[p] = *(const float2*)(bBase[p] + koff + 8 * EE);
            }
        }

#pragma unroll
        for (int s = 0; s < 4; s++) {
            uint4 bf0 = *(const uint4*)&Bp[wn * 2 + 0][s][lane][0];
            uint4 bf1 = *(const uint4*)&Bp[wn * 2 + 1][s][lane][0];
#pragma unroll
            for (int mt = 0; mt < 4; mt++) {
                uint4 af = *(const uint4*)&Ap[wm * 4 + mt][s][lane][0];
                mma8(acc[mt][0], af.x, af.y, af.z, af.w, bf0.x, bf0.y);
                mma8(acc[mt][1], af.x, af.y, af.z, af.w, bf0.z, bf0.w);
                mma8(acc[mt][2], af.x, af.y, af.z, af.w, bf1.x, bf1.y);
                mma8(acc[mt][3], af.x, af.y, af.z, af.w, bf1.z, bf1.w);
            }
        }
        __syncthreads();
    }

#pragma unroll
    for (int mt = 0; mt < 4; mt++) {
        int r0 = m0 + wm * 64 + mt * 16 + g;
        int r1 = r0 + 8;
        int b0i = r0 >> 12, s0i = r0 & (SS - 1);
        int b1i = r1 >> 12, s1i = r1 & (SS - 1);
#pragma unroll
        for (int nt = 0; nt < 4; nt++) {
            int n = n0 + wn * 32 + nt * 8 + 2 * t;
            int h = n >> 6, d = n & 63;
            float2 bi = *(const float2*)(bias + n);
            float2 o;
            o.x = (acc[mt][nt][0] + bi.x) * scale;
            o.y = (acc[mt][nt][1] + bi.y) * scale;
            *(float2*)(&Out[((size_t)(b0i * HH + h) * SS + s0i) * DD + d]) = o;
            o.x = (acc[mt][nt][2] + bi.x) * scale;
            o.y = (acc[mt][nt][3] + bi.y) * scale;
            *(float2*)(&Out[((size_t)(b1i * HH + h) * SS + s1i) * DD + d]) = o;
        }
    }
}

// ---------------------------------------------------------------------------
// Band attention (tf32 mma.sync), R13 math + software-pipelined staging:
// K/V double-buffered in smem (96KB total); chunk cg+1's LDG->STS issues
// BEFORE chunk cg's compute, so global latency hides under the mmas; ONE
// sync per chunk.  P feeds PV as raw f32 bits (bias cancels in P/l).
// Chunk loop uses exact [cgLo, cgHi] bounds (equivalent to the old skips).
// ---------------------------------------------------------------------------
#define QIDX(s, mq, ln) ((((s) * 8 + (mq)) * 32 + (ln)) * 4)
#define KIDX(s, np, ln) ((((s) * 4 + (np)) * 32 + (ln)) * 4)
#define SMEM_ATTN (96 * 1024)

__global__ __launch_bounds__(128)
void attn_mma(float* __restrict__ out)
{
    extern __shared__ uint32_t dsm[];
    uint32_t* Qf  = dsm;                 // 32KB: [s][mq][lane][4]
    uint32_t* Kf0 = dsm + 8192;          // 16KB
    uint32_t* Vf0 = dsm + 12288;         // 16KB
    uint32_t* Kf1 = dsm + 16384;         // 16KB
    uint32_t* Vf1 = dsm + 20480;         // 16KB

    const int bh = blockIdx.y;
    const int bb = bh >> 3;
    const int hh = bh & 7;
    const int i0 = blockIdx.x * 128;
    const int tid = threadIdx.x;
    const int w = tid >> 5;
    const int lane = tid & 31;
    const int g = lane >> 2;
    const int t = lane & 3;

    const float* qg = g_q + (size_t)bh * SS * DD;
    const float* kg = g_k + (size_t)bh * SS * DD;
    const float* vg = g_v + (size_t)bh * SS * DD;

    // Stage K/V chunk cg into the given buffers (raw f32 bits, no barrier).
    auto stage = [&](int cg, uint32_t* Kb, uint32_t* Vb) {
        const int j0 = i0 - WW + cg * 64;
        const float* kp = kg + (size_t)j0 * DD;
        const float* vp = vg + (size_t)j0 * DD;
#pragma unroll
        for (int p = 0; p < 8; p++) {
            int slot = w * 8 + p;
            int np = slot >> 3, s = slot & 7;
            const float* r0 = kp + (size_t)(16 * np + g) * DD + 8 * s + 2 * t;
            float2 x0 = *(const float2*)r0;
            float2 x1 = *(const float2*)(r0 + 8 * DD);
            uint4 u;
            u.x = __float_as_uint(x0.x); u.y = __float_as_uint(x0.y);
            u.z = __float_as_uint(x1.x); u.w = __float_as_uint(x1.y);
            *(uint4*)&Kb[KIDX(s, np, lane)] = u;
        }
#pragma unroll
        for (int p = 0; p < 8; p++) {
            int slot = w * 8 + p;
            int np = slot >> 3, s = slot & 7;
            const float* r0 = vp + (size_t)(8 * s + 2 * t) * DD;
            const float* r1 = r0 + DD;
            uint4 u;
            u.x = __float_as_uint(r0[16 * np + g]);
            u.y = __float_as_uint(r1[16 * np + g]);
            u.z = __float_as_uint(r0[16 * np + 8 + g]);
            u.w = __float_as_uint(r1[16 * np + 8 + g]);
            *(uint4*)&Vb[KIDX(s, np, lane)] = u;
        }
    };

    // Stage Q once (round-to-nearest tf32).
#pragma unroll
    for (int p = 0; p < 16; p++) {
        int slot = w * 16 + p;
        int mq = slot >> 3, s = slot & 7;
        const float* r0 = qg + (size_t)(i0 + 16 * mq + g) * DD + 8 * s + 2 * t;
        float2 x0 = *(const float2*)r0;
        float2 x1 = *(const float2*)(r0 + 8 * DD);
        uint4 u;
        u.x = f2tf(x0.x); u.y = f2tf(x1.x);
        u.z = f2tf(x0.y); u.w = f2tf(x1.y);
        *(uint4*)&Qf[QIDX(s, mq, lane)] = u;
    }

    float oacc[2][8][4];
#pragma unroll
    for (int mt = 0; mt < 2; mt++)
#pragma unroll
        for (int nt = 0; nt < 8; nt++)
#pragma unroll
            for (int i = 0; i < 4; i++) oacc[mt][nt][i] = 0.f;
    float lpA[2] = {0.f, 0.f}, lpB[2] = {0.f, 0.f};

    // Exact chunk bounds (j0 = i0-256+64cg in [0, SS-64]).
    const int cgLo = (i0 < WW) ? (WW - i0) / 64 : 0;
    const int cgHiRaw = (SS - 64 - i0 + WW) / 64;
    const int cgHi = cgHiRaw < 9 ? cgHiRaw : 9;

    stage(cgLo, Kf0, Vf0);
    __syncthreads();   // Q + first K/V visible

    for (int cg = cgLo; cg <= cgHi; cg++) {
        const int b = (cg - cgLo) & 1;
        uint32_t* Kb = b ? Kf1 : Kf0;
        uint32_t* Vb = b ? Vf1 : Vf0;

        // Prefetch chunk cg+1 into the idle buffers (overlaps compute).
        if (cg < cgHi) stage(cg + 1, b ? Kf0 : Kf1, b ? Vf0 : Vf1);

        // QK: S = Q @ K^T  (32 rows x 64 cols per warp)
        float sc[2][8][4];
#pragma unroll
        for (int mt = 0; mt < 2; mt++)
#pragma unroll
            for (int nt = 0; nt < 8; nt++)
#pragma unroll
                for (int i = 0; i < 4; i++) sc[mt][nt][i] = 0.f;
#pragma unroll
        for (int s = 0; s < 8; s++) {
            uint4 q0 = *(const uint4*)&Qf[QIDX(s, 2 * w + 0, lane)];
            uint4 q1 = *(const uint4*)&Qf[QIDX(s, 2 * w + 1, lane)];
#pragma unroll
            for (int np = 0; np < 4; np++) {
                uint4 u = *(const uint4*)&Kb[KIDX(s, np, lane)];
                mma8(sc[0][2 * np],     q0.x, q0.y, q0.z, q0.w, u.x, u.y);
                mma8(sc[0][2 * np + 1], q0.x, q0.y, q0.z, q0.w, u.z, u.w);
                mma8(sc[1][2 * np],     q1.x, q1.y, q1.z, q1.w, u.x, u.y);
                mma8(sc[1][2 * np + 1], q1.x, q1.y, q1.z, q1.w, u.z, u.w);
            }
        }

        // Band mask: valid iff 0 <= 64*cg + col - row <= 512.
        if (cg <= 1) {
#pragma unroll
            for (int mt = 0; mt < 2; mt++) {
                int lo = 32 * w + 16 * mt + g - 64 * cg;
#pragma unroll
                for (int nt = 0; nt < 8; nt++) {
                    int c0 = 8 * nt + 2 * t;
                    if (c0     < lo)     sc[mt][nt][0] = NEG;
                    if (c0 + 1 < lo)     sc[mt][nt][1] = NEG;
                    if (c0     < lo + 8) sc[mt][nt][2] = NEG;
                    if (c0 + 1 < lo + 8) sc[mt][nt][3] = NEG;
                }
            }
        } else if (cg >= 8) {
#pragma unroll
            for (int mt = 0; mt < 2; mt++) {
                int hi = 32 * w + 16 * mt + g + 512 - 64 * cg;
#pragma unroll
                for (int nt = 0; nt < 8; nt++) {
                    int c0 = 8 * nt + 2 * t;
                    if (c0     > hi)     sc[mt][nt][0] = NEG;
                    if (c0 + 1 > hi)     sc[mt][nt][1] = NEG;
                    if (c0     > hi + 8) sc[mt][nt][2] = NEG;
                    if (c0 + 1 > hi + 8) sc[mt][nt][3] = NEG;
                }
            }
        }

        // Direct exp (scores bounded; masked -> exp(-1e30) == 0 exactly).
#pragma unroll
        for (int mt = 0; mt < 2; mt++) {
#pragma unroll
            for (int nt = 0; nt < 8; nt++) {
                sc[mt][nt][0] = __expf(sc[mt][nt][0]);
                sc[mt][nt][1] = __expf(sc[mt][nt][1]);
                sc[mt][nt][2] = __expf(sc[mt][nt][2]);
                sc[mt][nt][3] = __expf(sc[mt][nt][3]);
                lpA[mt] += sc[mt][nt][0] + sc[mt][nt][1];
                lpB[mt] += sc[mt][nt][2] + sc[mt][nt][3];
            }
        }

        // PV: O += P @ V.  P raw f32 bits (truncation bias cancels in P/l).
#pragma unroll
        for (int s = 0; s < 8; s++) {
            uint32_t a[2][4];
#pragma unroll
            for (int mt = 0; mt < 2; mt++) {
                a[mt][0] = __float_as_uint(sc[mt][s][0]);
                a[mt][1] = __float_as_uint(sc[mt][s][2]);
                a[mt][2] = __float_as_uint(sc[mt][s][1]);
                a[mt][3] = __float_as_uint(sc[mt][s][3]);
            }
#pragma unroll
            for (int np = 0; np < 4; np++) {
                uint4 u = *(const uint4*)&Vb[KIDX(s, np, lane)];
                mma8(oacc[0][2 * np],     a[0][0], a[0][1], a[0][2], a[0][3], u.x, u.y);
                mma8(oacc[0][2 * np + 1], a[0][0], a[0][1], a[0][2], a[0][3], u.z, u.w);
                mma8(oacc[1][2 * np],     a[1][0], a[1][1], a[1][2], a[1][3], u.x, u.y);
                mma8(oacc[1][2 * np + 1], a[1][0], a[1][1], a[1][2], a[1][3], u.z, u.w);
            }
        }

        __syncthreads();   // next-chunk stores visible; this-buffer reads done
    }

    // Epilogue: quad-reduce row sums once, then scaled stores.
#pragma unroll
    for (int mt = 0; mt < 2; mt++) {
        float sA = lpA[mt], sB = lpB[mt];
        sA += __shfl_xor_sync(0xffffffffu, sA, 1);
        sA += __shfl_xor_sync(0xffffffffu, sA, 2);
        sB += __shfl_xor_sync(0xffffffffu, sB, 1);
        sB += __shfl_xor_sync(0xffffffffu, sB, 2);
        float iA = 1.f / sA, iB = 1.f / sB;
        size_t baseA = (size_t)(i0 + 32 * w + 16 * mt + g) * 2048
                     + (size_t)(bb * 512 + hh * 64);
        size_t baseB = baseA + (size_t)8 * 2048;
#pragma unroll
        for (int nt = 0; nt < 8; nt++) {
            int d = 8 * nt + 2 * t;
            float2 o;
            o.x = oacc[mt][nt][0] * iA; o.y = oacc[mt][nt][1] * iA;
            *(float2*)(out + baseA + d) = o;
            o.x = oacc[mt][nt][2] * iB; o.y = oacc[mt][nt][3] * iB;
            *(float2*)(out + baseB + d) = o;
        }
    }
}

// ---------------------------------------------------------------------------
extern "C" void kernel_launch(void* const* d_in, const int* in_sizes, int n_in,
                              void* d_out, int out_size)
{
    (void)in_sizes; (void)n_in; (void)out_size;
    const float* query = (const float*)d_in[0];
    const float* key   = (const float*)d_in[1];
    const float* value = (const float*)d_in[2];
    const float* Wq = (const float*)d_in[4];
    const float* bq = (const float*)d_in[5];
    const float* Wk = (const float*)d_in[6];
    const float* bk = (const float*)d_in[7];
    const float* Wv = (const float*)d_in[8];
    const float* bv = (const float*)d_in[9];
    float* out = (float*)d_out;

    float *qp, *kp, *vp;
    cudaGetSymbolAddress((void**)&qp, g_q);
    cudaGetSymbolAddress((void**)&kp, g_k);
    cudaGetSymbolAddress((void**)&vp, g_v);

    static int smem_set = 0;
    if (!smem_set) {
        cudaFuncSetAttribute(attn_mma,
                             cudaFuncAttributeMaxDynamicSharedMemorySize,
                             SMEM_ATTN);
        smem_set = 1;
    }

    dim3 gp(EE / 128, (BB * SS) / 128, 3);   // fused Q/K/V projections
    proj_mma<<<gp, 256>>>(query, key, value, Wq, Wk, Wv, bq, bk, bv, qp, kp, vp);

    attn_mma<<<dim3(SS / 128, BHN), 128, SMEM_ATTN>>>(out);
}

// round 16
// speedup vs baseline: 1.4657x; 1.4357x over previous
#include <cuda_runtime.h>
#include <cuda_fp16.h>
#include <math.h>
#include <stdint.h>

#define BB 4
#define SS 4096
#define EE 512
#define HH 8
#define DD 64
#define WW 256
#define BHN (BB*HH)
#define NEG (-1e30f)

// Scratch (fp16): q/k in [b*H+h][s][d]; v TRANSPOSED in [b*H+h][d][s].
__device__ __half g_q[(size_t)BHN * SS * DD];
__device__ __half g_k[(size_t)BHN * SS * DD];
__device__ __half g_vt[(size_t)BHN * DD * SS];

__device__ __forceinline__ uint32_t f2h2(float lo, float hi) {
    __half2 h = __floats2half2_rn(lo, hi);
    return *(uint32_t*)&h;
}

// m16n8k16 fp16 mma, fp32 accumulate. A row-major, B col-major.
__device__ __forceinline__ void mma16(float* c,
                                      uint32_t a0, uint32_t a1, uint32_t a2, uint32_t a3,
                                      uint32_t b0, uint32_t b1) {
    asm volatile(
        "mma.sync.aligned.m16n8k16.row.col.f32.f16.f16.f32 "
        "{%0,%1,%2,%3},{%4,%5,%6,%7},{%8,%9},{%0,%1,%2,%3};"
        : "+f"(c[0]), "+f"(c[1]), "+f"(c[2]), "+f"(c[3])
        : "r"(a0), "r"(a1), "r"(a2), "r"(a3), "r"(b0), "r"(b1));
}

// ---------------------------------------------------------------------------
// Fused projection GEMMs (fp16 m16n8k16): blockIdx.z in {0,1,2} = Q,K,V.
// C = (X @ W^T + bias) * scale; Q,K written fp16 [bh][s][d]; V written
// fp16 TRANSPOSED [bh][d][s].
// 128x128 tile, K-chunk 32 (2 k-steps of 16), 8 warps (2m x 4n).
// Fragment-packed fp16 smem slots; all staging LDG.64; register prefetch.
// ---------------------------------------------------------------------------
__global__ __launch_bounds__(256, 2)
void proj_mma(const float* __restrict__ Xq, const float* __restrict__ Xk,
              const float* __restrict__ Xv,
              const float* __restrict__ Wq, const float* __restrict__ Wk,
              const float* __restrict__ Wv,
              const float* __restrict__ bq, const float* __restrict__ bk,
              const float* __restrict__ bv,
              __half* __restrict__ Oq, __half* __restrict__ Ok,
              __half* __restrict__ Ovt)
{
    __shared__ uint32_t Ah[8][2][32][4];   // 8KB: A fragments (mt, kstep)
    __shared__ uint32_t Bh[8][2][32][4];   // 8KB: B fragment pairs (np, kstep)

    const int z = blockIdx.z;
    const float* X    = (z == 0) ? Xq : (z == 1) ? Xk : Xv;
    const float* Wm   = (z == 0) ? Wq : (z == 1) ? Wk : Wv;
    const float* bias = (z == 0) ? bq : (z == 1) ? bk : bv;
    const float scale = (z == 0) ? 0.125f : 1.0f;

    const int tid = threadIdx.x;
    const int lane = tid & 31;
    const int w = tid >> 5;
    const int wm = w >> 2;
    const int wn = w & 3;
    const int m0 = blockIdx.y * 128;
    const int n0 = blockIdx.x * 128;
    const int g = lane >> 2;
    const int t = lane & 3;

    float acc[4][4][4];
#pragma unroll
    for (int mt = 0; mt < 4; mt++)
#pragma unroll
        for (int nt = 0; nt < 4; nt++)
#pragma unroll
            for (int i = 0; i < 4; i++) acc[mt][nt][i] = 0.f;

    // Per-thread slot bases.  A slot p: (mt, sA); B slot p: (np, sB).
    const float* aB[2];
    const float* bB[2];
#pragma unroll
    for (int p = 0; p < 2; p++) {
        int idx = w * 2 + p;
        int mt = idx >> 1, sA = idx & 1;
        aB[p] = X + (size_t)(m0 + 16 * mt + g) * EE + 16 * sA + 2 * t;
        int np = idx >> 1, sB = idx & 1;
        bB[p] = Wm + (size_t)(n0 + 16 * np + g) * EE + 16 * sB + 2 * t;
    }

    // Prefetch registers: per slot 4 float2 at (r,c0)(r+8,c0)(r,c0+8)(r+8,c0+8)
    float2 pa[2][4], pb[2][4];
#pragma unroll
    for (int p = 0; p < 2; p++) {
        pa[p][0] = *(const float2*)(aB[p]);
        pa[p][1] = *(const float2*)(aB[p] + 8 * EE);
        pa[p][2] = *(const float2*)(aB[p] + 8);
        pa[p][3] = *(const float2*)(aB[p] + 8 * EE + 8);
        pb[p][0] = *(const float2*)(bB[p]);
        pb[p][1] = *(const float2*)(bB[p] + 8);
        pb[p][2] = *(const float2*)(bB[p] + 8 * EE);
        pb[p][3] = *(const float2*)(bB[p] + 8 * EE + 8);
    }

    for (int kc = 0; kc < 16; kc++) {
        // Store prefetched chunk into fragment slots (STS.128, conflict-free).
#pragma unroll
        for (int p = 0; p < 2; p++) {
            int idx = w * 2 + p;
            int f = idx >> 1, s = idx & 1;
            uint4 u;
            u.x = f2h2(pa[p][0].x, pa[p][0].y);   // a0: row g,  k 2t..2t+1
            u.y = f2h2(pa[p][1].x, pa[p][1].y);   // a1: row g+8
            u.z = f2h2(pa[p][2].x, pa[p][2].y);   // a2: row g,  k 2t+8..9
            u.w = f2h2(pa[p][3].x, pa[p][3].y);   // a3: row g+8
            *(uint4*)&Ah[f][s][lane][0] = u;
            uint4 v;
            v.x = f2h2(pb[p][0].x, pb[p][0].y);   // b0 nt even (n=16np+g)
            v.y = f2h2(pb[p][1].x, pb[p][1].y);   // b1 nt even
            v.z = f2h2(pb[p][2].x, pb[p][2].y);   // b0 nt odd  (n=16np+8+g)
            v.w = f2h2(pb[p][3].x, pb[p][3].y);   // b1 nt odd
            *(uint4*)&Bh[f][s][lane][0] = v;
        }
        __syncthreads();

        // Prefetch chunk kc+1 (LDGs overlap the mma compute below).
        if (kc + 1 < 16) {
            const int koff = (kc + 1) * 32;
#pragma unroll
            for (int p = 0; p < 2; p++) {
                pa[p][0] = *(const float2*)(aB[p] + koff);
                pa[p][1] = *(const float2*)(aB[p] + koff + 8 * EE);
                pa[p][2] = *(const float2*)(aB[p] + koff + 8);
                pa[p][3] = *(const float2*)(aB[p] + koff + 8 * EE + 8);
                pb[p][0] = *(const float2*)(bB[p] + koff);
                pb[p][1] = *(const float2*)(bB[p] + koff + 8);
                pb[p][2] = *(const float2*)(bB[p] + koff + 8 * EE);
                pb[p][3] = *(const float2*)(bB[p] + koff + 8 * EE + 8);
            }
        }

        // Compute: 2 k-steps of 16; 16 mmas per step per warp.
#pragma unroll
        for (int s = 0; s < 2; s++) {
            uint4 bf0 = *(const uint4*)&Bh[wn * 2 + 0][s][lane][0];
            uint4 bf1 = *(const uint4*)&Bh[wn * 2 + 1][s][lane][0];
#pragma unroll
            for (int mt = 0; mt < 4; mt++) {
                uint4 af = *(const uint4*)&Ah[wm * 4 + mt][s][lane][0];
                mma16(acc[mt][0], af.x, af.y, af.z, af.w, bf0.x, bf0.y);
                mma16(acc[mt][1], af.x, af.y, af.z, af.w, bf0.z, bf0.w);
                mma16(acc[mt][2], af.x, af.y, af.z, af.w, bf1.x, bf1.y);
                mma16(acc[mt][3], af.x, af.y, af.z, af.w, bf1.z, bf1.w);
            }
        }
        __syncthreads();
    }

    // Epilogue: bias + scale, convert fp16, permuted store.
#pragma unroll
    for (int mt = 0; mt < 4; mt++) {
        int r0 = m0 + wm * 64 + mt * 16 + g;
        int r1 = r0 + 8;
        int b0i = r0 >> 12, s0i = r0 & (SS - 1);
        int b1i = r1 >> 12, s1i = r1 & (SS - 1);
#pragma unroll
        for (int nt = 0; nt < 4; nt++) {
            int n = n0 + wn * 32 + nt * 8 + 2 * t;
            int h = n >> 6, d = n & 63;
            float2 bi = *(const float2*)(bias + n);
            float v00 = (acc[mt][nt][0] + bi.x) * scale;
            float v01 = (acc[mt][nt][1] + bi.y) * scale;
            float v10 = (acc[mt][nt][2] + bi.x) * scale;
            float v11 = (acc[mt][nt][3] + bi.y) * scale;
            if (z != 2) {
                __half* Out = (z == 0) ? Oq : Ok;
                *(uint32_t*)&Out[((size_t)(b0i * HH + h) * SS + s0i) * DD + d] =
                    f2h2(v00, v01);
                *(uint32_t*)&Out[((size_t)(b1i * HH + h) * SS + s1i) * DD + d] =
                    f2h2(v10, v11);
            } else {
                // V transposed: Ovt[(bh*64 + d)*SS + s]
                size_t c0 = ((size_t)((b0i * HH + h) * 64 + d)) * SS;
                size_t c1 = ((size_t)((b1i * HH + h) * 64 + d)) * SS;
                Ovt[c0 + s0i]      = __float2half_rn(v00);
                Ovt[c0 + SS + s0i] = __float2half_rn(v01);
                Ovt[c1 + s1i]      = __float2half_rn(v10);
                Ovt[c1 + SS + s1i] = __float2half_rn(v11);
            }
        }
    }
}

// ---------------------------------------------------------------------------
// Band attention (fp16 m16n8k16): 128-query-row blocks, 4 warps x 32 rows.
// Q staged once (16KB); K/V double-buffered (8KB each x2), software-pipelined
// staging (chunk cg+1 LDG->STS before compute of cg), one sync per chunk.
// q/k/v scratch already fp16 -> staging is pure LDG.32 -> STS.128, no cvt.
// P stays in registers: QK C-fragments ARE the PV A-fragments (no permute).
// Direct exp; single epilogue row-sum reduction.  smem = 48KB.
// ---------------------------------------------------------------------------
#define QIDX(s, mq, ln) ((((s) * 8 + (mq)) * 32 + (ln)) * 4)
#define KIDX(s, np, ln) ((((s) * 4 + (np)) * 32 + (ln)) * 4)
#define SMEM_ATTN (48 * 1024)

__global__ __launch_bounds__(128)
void attn_mma(float* __restrict__ out)
{
    extern __shared__ uint32_t dsm[];
    uint32_t* Qf  = dsm;                 // 16KB: [s4][mq8][lane][4]
    uint32_t* Kf0 = dsm + 4096;          // 8KB:  [s4][np4][lane][4]
    uint32_t* Vf0 = dsm + 6144;          // 8KB
    uint32_t* Kf1 = dsm + 8192;          // 8KB
    uint32_t* Vf1 = dsm + 10240;         // 8KB

    const int bh = blockIdx.y;
    const int bb = bh >> 3;
    const int hh = bh & 7;
    const int i0 = blockIdx.x * 128;
    const int tid = threadIdx.x;
    const int w = tid >> 5;
    const int lane = tid & 31;
    const int g = lane >> 2;
    const int t = lane & 3;

    const __half* qg = g_q  + (size_t)bh * SS * DD;
    const __half* kg = g_k  + (size_t)bh * SS * DD;
    const __half* vt = g_vt + (size_t)bh * DD * SS;

    // Stage K/V chunk cg (64 keys) into the given buffers.  Pure LDG.32.
    auto stage = [&](int cg, uint32_t* Kb, uint32_t* Vb) {
        const int j0 = i0 - WW + cg * 64;
        const __half* kp = kg + (size_t)j0 * DD;
        const __half* vp = vt + j0;
#pragma unroll
        for (int p = 0; p < 4; p++) {
            int idx = w * 4 + p;
            int np = idx >> 2, s = idx & 3;
            int n = 16 * np + g;          // key row within chunk
            int c0 = 16 * s + 2 * t;      // d column
            uint4 u;
            u.x = *(const uint32_t*)(kp + (size_t)n * DD + c0);
            u.y = *(const uint32_t*)(kp + (size_t)n * DD + c0 + 8);
            u.z = *(const uint32_t*)(kp + (size_t)(n + 8) * DD + c0);
            u.w = *(const uint32_t*)(kp + (size_t)(n + 8) * DD + c0 + 8);
            *(uint4*)&Kb[KIDX(s, np, lane)] = u;
        }
#pragma unroll
        for (int p = 0; p < 4; p++) {
            int idx = w * 4 + p;
            int np = idx >> 2, s = idx & 3;
            int n = 16 * np + g;          // d row of V^T
            int c0 = 16 * s + 2 * t;      // j column
            uint4 u;
            u.x = *(const uint32_t*)(vp + (size_t)n * SS + c0);
            u.y = *(const uint32_t*)(vp + (size_t)n * SS + c0 + 8);
            u.z = *(const uint32_t*)(vp + (size_t)(n + 8) * SS + c0);
            u.w = *(const uint32_t*)(vp + (size_t)(n + 8) * SS + c0 + 8);
            *(uint4*)&Vb[KIDX(s, np, lane)] = u;
        }
    };

    // Stage Q once: 32 (s,mq) slots, 8 per warp.
#pragma unroll
    for (int p = 0; p < 8; p++) {
        int idx = w * 8 + p;
        int mq = idx >> 2, s = idx & 3;
        const __half* r0 = qg + (size_t)(i0 + 16 * mq + g) * DD + 16 * s + 2 * t;
        uint4 u;
        u.x = *(const uint32_t*)(r0);               // a0: row g,  k 2t..+1
        u.y = *(const uint32_t*)(r0 + 8 * DD);      // a1: row g+8
        u.z = *(const uint32_t*)(r0 + 8);           // a2: row g,  k 2t+8..9
        u.w = *(const uint32_t*)(r0 + 8 * DD + 8);  // a3: row g+8
        *(uint4*)&Qf[QIDX(s, mq, lane)] = u;
    }

    float oacc[2][8][4];
#pragma unroll
    for (int mt = 0; mt < 2; mt++)
#pragma unroll
        for (int nt = 0; nt < 8; nt++)
#pragma unroll
            for (int i = 0; i < 4; i++) oacc[mt][nt][i] = 0.f;
    float lpA[2] = {0.f, 0.f}, lpB[2] = {0.f, 0.f};

    // Exact chunk bounds (j0 = i0-256+64cg in [0, SS-64]).
    const int cgLo = (i0 < WW) ? (WW - i0) / 64 : 0;
    const int cgHiRaw = (SS - 64 - i0 + WW) / 64;
    const int cgHi = cgHiRaw < 9 ? cgHiRaw : 9;

    stage(cgLo, Kf0, Vf0);
    __syncthreads();   // Q + first K/V visible

    for (int cg = cgLo; cg <= cgHi; cg++) {
        const int b = (cg - cgLo) & 1;
        uint32_t* Kb = b ? Kf1 : Kf0;
        uint32_t* Vb = b ? Vf1 : Vf0;

        if (cg < cgHi) stage(cg + 1, b ? Kf0 : Kf1, b ? Vf0 : Vf1);

        // QK: S = Q @ K^T  (32 rows x 64 cols per warp; 4 k-steps of 16)
        float sc[2][8][4];
#pragma unroll
        for (int mt = 0; mt < 2; mt++)
#pragma unroll
            for (int nt = 0; nt < 8; nt++)
#pragma unroll
                for (int i = 0; i < 4; i++) sc[mt][nt][i] = 0.f;
#pragma unroll
        for (int s = 0; s < 4; s++) {
            uint4 q0 = *(const uint4*)&Qf[QIDX(s, 2 * w + 0, lane)];
            uint4 q1 = *(const uint4*)&Qf[QIDX(s, 2 * w + 1, lane)];
#pragma unroll
            for (int np = 0; np < 4; np++) {
                uint4 u = *(const uint4*)&Kb[KIDX(s, np, lane)];
                mma16(sc[0][2 * np],     q0.x, q0.y, q0.z, q0.w, u.x, u.y);
                mma16(sc[0][2 * np + 1], q0.x, q0.y, q0.z, q0.w, u.z, u.w);
                mma16(sc[1][2 * np],     q1.x, q1.y, q1.z, q1.w, u.x, u.y);
                mma16(sc[1][2 * np + 1], q1.x, q1.y, q1.z, q1.w, u.z, u.w);
            }
        }

        // Band mask: valid iff 0 <= 64*cg + col - row <= 512.
        if (cg <= 1) {
#pragma unroll
            for (int mt = 0; mt < 2; mt++) {
                int lo = 32 * w + 16 * mt + g - 64 * cg;
#pragma unroll
                for (int nt = 0; nt < 8; nt++) {
                    int c0 = 8 * nt + 2 * t;
                    if (c0     < lo)     sc[mt][nt][0] = NEG;
                    if (c0 + 1 < lo)     sc[mt][nt][1] = NEG;
                    if (c0     < lo + 8) sc[mt][nt][2] = NEG;
                    if (c0 + 1 < lo + 8) sc[mt][nt][3] = NEG;
                }
            }
        } else if (cg >= 8) {
#pragma unroll
            for (int mt = 0; mt < 2; mt++) {
                int hi = 32 * w + 16 * mt + g + 512 - 64 * cg;
#pragma unroll
                for (int nt = 0; nt < 8; nt++) {
                    int c0 = 8 * nt + 2 * t;
                    if (c0     > hi)     sc[mt][nt][0] = NEG;
                    if (c0 + 1 > hi)     sc[mt][nt][1] = NEG;
                    if (c0     > hi + 8) sc[mt][nt][2] = NEG;
                    if (c0 + 1 > hi + 8) sc[mt][nt][3] = NEG;
                }
            }
        }

        // Direct exp (scores bounded; masked -> exp(-1e30) == 0 exactly).
#pragma unroll
        for (int mt = 0; mt < 2; mt++) {
#pragma unroll
            for (int nt = 0; nt < 8; nt++) {
                sc[mt][nt][0] = __expf(sc[mt][nt][0]);
                sc[mt][nt][1] = __expf(sc[mt][nt][1]);
                sc[mt][nt][2] = __expf(sc[mt][nt][2]);
                sc[mt][nt][3] = __expf(sc[mt][nt][3]);
                lpA[mt] += sc[mt][nt][0] + sc[mt][nt][1];
                lpB[mt] += sc[mt][nt][2] + sc[mt][nt][3];
            }
        }

        // PV: O += P @ V.  QK C-frags ARE the PV A-frags (j k-step s uses
        // score tiles nt=2s, 2s+1); convert to fp16 pairs in registers.
#pragma unroll
        for (int s = 0; s < 4; s++) {
            uint32_t a[2][4];
#pragma unroll
            for (int mt = 0; mt < 2; mt++) {
                a[mt][0] = f2h2(sc[mt][2 * s][0],     sc[mt][2 * s][1]);
                a[mt][1] = f2h2(sc[mt][2 * s][2],     sc[mt][2 * s][3]);
                a[mt][2] = f2h2(sc[mt][2 * s + 1][0], sc[mt][2 * s + 1][1]);
                a[mt][3] = f2h2(sc[mt][2 * s + 1][2], sc[mt][2 * s + 1][3]);
            }
#pragma unroll
            for (int np = 0; np < 4; np++) {
                uint4 u = *(const uint4*)&Vb[KIDX(s, np, lane)];
                mma16(oacc[0][2 * np],     a[0][0], a[0][1], a[0][2], a[0][3], u.x, u.y);
                mma16(oacc[0][2 * np + 1], a[0][0], a[0][1], a[0][2], a[0][3], u.z, u.w);
                mma16(oacc[1][2 * np],     a[1][0], a[1][1], a[1][2], a[1][3], u.x, u.y);
                mma16(oacc[1][2 * np + 1], a[1][0], a[1][1], a[1][2], a[1][3], u.z, u.w);
            }
        }

        __syncthreads();   // next-chunk stores visible; this-buffer reads done
    }

    // Epilogue: quad-reduce row sums once, then scaled stores.
#pragma unroll
    for (int mt = 0; mt < 2; mt++) {
        float sA = lpA[mt], sB = lpB[mt];
        sA += __shfl_xor_sync(0xffffffffu, sA, 1);
        sA += __shfl_xor_sync(0xffffffffu, sA, 2);
        sB += __shfl_xor_sync(0xffffffffu, sB, 1);
        sB += __shfl_xor_sync(0xffffffffu, sB, 2);
        float iA = 1.f / sA, iB = 1.f / sB;
        size_t baseA = (size_t)(i0 + 32 * w + 16 * mt + g) * 2048
                     + (size_t)(bb * 512 + hh * 64);
        size_t baseB = baseA + (size_t)8 * 2048;
#pragma unroll
        for (int nt = 0; nt < 8; nt++) {
            int d = 8 * nt + 2 * t;
            float2 o;
            o.x = oacc[mt][nt][0] * iA; o.y = oacc[mt][nt][1] * iA;
            *(float2*)(out + baseA + d) = o;
            o.x = oacc[mt][nt][2] * iB; o.y = oacc[mt][nt][3] * iB;
            *(float2*)(out + baseB + d) = o;
        }
    }
}

// ---------------------------------------------------------------------------
extern "C" void kernel_launch(void* const* d_in, const int* in_sizes, int n_in,
                              void* d_out, int out_size)
{
    (void)in_sizes; (void)n_in; (void)out_size;
    const float* query = (const float*)d_in[0];
    const float* key   = (const float*)d_in[1];
    const float* value = (const float*)d_in[2];
    const float* Wq = (const float*)d_in[4];
    const float* bq = (const float*)d_in[5];
    const float* Wk = (const float*)d_in[6];
    const float* bk = (const float*)d_in[7];
    const float* Wv = (const float*)d_in[8];
    const float* bv = (const float*)d_in[9];
    float* out = (float*)d_out;

    __half *qp, *kp, *vtp;
    cudaGetSymbolAddress((void**)&qp,  g_q);
    cudaGetSymbolAddress((void**)&kp,  g_k);
    cudaGetSymbolAddress((void**)&vtp, g_vt);

    static int smem_set = 0;
    if (!smem_set) {
        cudaFuncSetAttribute(attn_mma,
                             cudaFuncAttributeMaxDynamicSharedMemorySize,
                             SMEM_ATTN);
        smem_set = 1;
    }

    dim3 gp(EE / 128, (BB * SS) / 128, 3);   // fused Q/K/V projections
    proj_mma<<<gp, 256>>>(query, key, value, Wq, Wk, Wv, bq, bk, bv,
                          qp, kp, vtp);

    attn_mma<<<dim3(SS / 128, BHN), 128, SMEM_ATTN>>>(out);
}